// round 6
// baseline (speedup 1.0000x reference)
#include <cuda_runtime.h>
#include <cuda_bf16.h>
#include <cstdint>

// ---------------- problem constants ----------------
#define B_ 256
#define T_ 512
#define D_ 64
#define H_ 512
#define G_ 2048
#define NCTA 64
#define NTHR 512
#define NW 16             // warps per CTA, each owns 16 rows of M=256
#define HC 8              // h-columns per CTA (32 gate cols = 4 gates x 8)
#define NITEM 18          // 9 chunks x 2 planes, 32KB each
#define RD 4              // pipeline ring depth
#define BROW 1168         // padded B row bytes (9*128 + 16)
#define BPLANE (32 * BROW)

// ---------------- dynamic SMEM layout (bytes) ----------------
#define SM_MBF 0                         // 4 full barriers
#define SM_MBE 64                        // 4 empty barriers
#define SM_BIAS 128
#define SM_A 1024                        // ring: 4 x 32768 = 131072
#define SM_B (SM_A + 131072)
#define SMEM_BYTES (SM_B + 2 * BPLANE)   // 206848

// ---------------- persistent device state ----------------
// h K-blocked swizzled: [buf][plane][kc][row][64 cols (swizzled within 128B row)]
__device__ __align__(128) __nv_bfloat16 g_hA[2][2][8][256][64];
// x per-step K-blocked swizzled: [plane][t][row][64]
__device__ __align__(128) __nv_bfloat16 g_xA[2][T_][256][64];
__device__ unsigned g_count, g_gen;

// ---------------- math helpers ----------------
__device__ __forceinline__ float softplus_(float r) {
    return (r > 15.f) ? r : log1pf(expf(r));
}
__device__ __forceinline__ float sample_(float mu, float rho, float eps) {
    return mu + softplus_(rho) * eps;
}
__device__ __forceinline__ float sigmoid_(float x) {
    return __fdividef(1.f, 1.f + __expf(-x));
}
__device__ __forceinline__ float tanh_(float x) {
    return __fdividef(2.f, 1.f + __expf(-2.f * x)) - 1.f;
}

// ---------------- PTX helpers ----------------
__device__ __forceinline__ uint32_t smem_u32_(const void* p) {
    uint32_t a;
    asm("{ .reg .u64 t; cvta.to.shared.u64 t, %1; cvt.u32.u64 %0, t; }"
        : "=r"(a) : "l"(p));
    return a;
}
__device__ __forceinline__ void mbar_init_(uint32_t a, uint32_t cnt) {
    asm volatile("mbarrier.init.shared.b64 [%0], %1;" :: "r"(a), "r"(cnt) : "memory");
}
__device__ __forceinline__ void mbar_inval_(uint32_t a) {
    asm volatile("mbarrier.inval.shared.b64 [%0];" :: "r"(a) : "memory");
}
__device__ __forceinline__ void mbar_expect_tx_(uint32_t a, uint32_t bytes) {
    asm volatile("mbarrier.arrive.expect_tx.shared.b64 _, [%0], %1;"
                 :: "r"(a), "r"(bytes) : "memory");
}
__device__ __forceinline__ void mbar_arrive_(uint32_t a) {
    asm volatile("mbarrier.arrive.shared.b64 _, [%0];" :: "r"(a) : "memory");
}
__device__ __forceinline__ void mbar_wait_(uint32_t a, uint32_t parity) {
    uint32_t done;
    asm volatile(
        "{\n\t.reg .pred p;\n\t"
        "mbarrier.try_wait.parity.acquire.cta.shared::cta.b64 p, [%1], %2;\n\t"
        "selp.b32 %0, 1, 0, p;\n\t}"
        : "=r"(done) : "r"(a), "r"(parity) : "memory");
    if (!done) {
        asm volatile(
            "{\n\t.reg .pred P1;\n\t"
            "W_%=:\n\t"
            "mbarrier.try_wait.parity.acquire.cta.shared::cta.b64 P1, [%0], %1, 0x989680;\n\t"
            "@P1 bra.uni D_%=;\n\t"
            "bra.uni W_%=;\n\t"
            "D_%=:\n\t}"
            :: "r"(a), "r"(parity) : "memory");
    }
}
__device__ __forceinline__ void bulk_g2s_(uint32_t dst, const void* src,
                                          uint32_t bytes, uint32_t mbar) {
    asm volatile(
        "cp.async.bulk.shared::cluster.global.mbarrier::complete_tx::bytes "
        "[%0], [%1], %2, [%3];"
        :: "r"(dst), "l"(src), "r"(bytes), "r"(mbar) : "memory");
}

#define LDM4(R, A) \
    asm volatile("ldmatrix.sync.aligned.m8n8.x4.shared.b16 {%0,%1,%2,%3}, [%4];" \
        : "=r"((R)[0]), "=r"((R)[1]), "=r"((R)[2]), "=r"((R)[3]) : "r"(A))

#define MMA(Cf, Af, Bf0, Bf1) \
    asm volatile("mma.sync.aligned.m16n8k16.row.col.f32.bf16.bf16.f32 " \
        "{%0,%1,%2,%3}, {%4,%5,%6,%7}, {%8,%9}, {%0,%1,%2,%3};" \
        : "+f"((Cf)[0]), "+f"((Cf)[1]), "+f"((Cf)[2]), "+f"((Cf)[3]) \
        : "r"((Af)[0]), "r"((Af)[1]), "r"((Af)[2]), "r"((Af)[3]), \
          "r"(Bf0), "r"(Bf1))

extern "C" __global__ void bar_init_kernel() {
    g_count = 0;
    g_gen = 0;
}

// ---------------- grid barrier ----------------
__device__ __forceinline__ void grid_sync_(unsigned target) {
    __syncthreads();
    if (threadIdx.x == 0) {
        __threadfence();
        unsigned a = atomicAdd(&g_count, 1u);
        if (a == NCTA - 1) {
            g_count = 0;
            __threadfence();
            atomicExch(&g_gen, target);
        } else {
            unsigned g;
            do {
                asm volatile("ld.global.cg.u32 %0, [%1];" : "=r"(g) : "l"(&g_gen));
                if (g >= target) break;
                __nanosleep(32);
            } while (1);
        }
        __threadfence();
    }
    __syncthreads();
}

// chunk order: x first (no cross-CTA dependency), then h chunks
__constant__ int c_order_[9] = {8, 0, 1, 2, 3, 4, 5, 6, 7};

// issue one 32KB item (chunk plane) into ring slot s
__device__ __forceinline__ void issue_item_(uint32_t sbase, int s, int ch,
                                            int plane, int t, uint32_t mb) {
    mbar_expect_tx_(mb, 32768u);
    const char* src;
    if (ch < 8)
        src = (const char*)g_hA + ((((size_t)(t & 1)) * 2 + plane) * 8 + ch) * 32768;
    else
        src = (const char*)g_xA + ((size_t)plane * T_ + t) * 32768;
    bulk_g2s_(sbase + SM_A + (uint32_t)s * 32768u, src, 32768u, mb);
}

// ---------------- main persistent kernel ----------------
extern "C" __global__ void __launch_bounds__(NTHR, 1)
lstm_hmma(const float* __restrict__ x,
          const float* __restrict__ wih_mu, const float* __restrict__ wih_rho,
          const float* __restrict__ wih_eps,
          const float* __restrict__ whh_mu, const float* __restrict__ whh_rho,
          const float* __restrict__ whh_eps,
          const float* __restrict__ b_mu,   const float* __restrict__ b_rho,
          const float* __restrict__ b_eps,
          const float* __restrict__ lin_w,  const float* __restrict__ lin_b,
          float* __restrict__ out)
{
    extern __shared__ char smem[];
    const uint32_t sbase = smem_u32_(smem);
    uint32_t mb_f[RD], mb_e[RD];
    #pragma unroll
    for (int s = 0; s < RD; s++) {
        mb_f[s] = sbase + SM_MBF + s * 8;
        mb_e[s] = sbase + SM_MBE + s * 8;
    }
    float* bias_s = (float*)(smem + SM_BIAS);

    const int tid  = threadIdx.x;
    const int lane = tid & 31;
    const int w    = tid >> 5;
    const int cta  = blockIdx.x;
    const int j0   = cta * HC;

    if (tid == 0) {
        #pragma unroll
        for (int s = 0; s < RD; s++) {
            mbar_init_(mb_f[s], 1);
            mbar_init_(mb_e[s], NW);
        }
    }

    // ---- sample W into SMEM B planes: rows n (32), cols k (576), padded ----
    for (int idx = tid; idx < 32 * 576; idx += NTHR) {
        int n = idx / 576, k = idx - n * 576;
        int col = (n >> 3) * H_ + j0 + (n & 7);
        float wv;
        if (k < 512) {
            int gi = k * G_ + col;
            wv = sample_(whh_mu[gi], whh_rho[gi], whh_eps[gi]);
        } else {
            int gi = (k - 512) * G_ + col;
            wv = sample_(wih_mu[gi], wih_rho[gi], wih_eps[gi]);
        }
        __nv_bfloat16 hi = __float2bfloat16(wv);
        __nv_bfloat16 lo = __float2bfloat16(wv - __bfloat162float(hi));
        *(__nv_bfloat16*)(smem + SM_B + 0 * BPLANE + n * BROW + k * 2) = hi;
        *(__nv_bfloat16*)(smem + SM_B + 1 * BPLANE + n * BROW + k * 2) = lo;
    }
    if (tid < 32) {
        int col = (tid >> 3) * H_ + j0 + (tid & 7);
        bias_s[tid] = sample_(b_mu[col], b_rho[col], b_eps[col]);
    }

    // ---- build swizzled x planes + zero h buf0 (grid-wide) ----
    {
        const int gtid = cta * NTHR + tid;
        const int gn = NCTA * NTHR;
        for (int i = gtid; i < B_ * T_ * D_; i += gn) {
            int d = i & 63, r = i >> 6;
            int t = r & 511, b = r >> 9;            // x is [b][t][d]
            float v = __ldg(&x[i]);
            __nv_bfloat16 hi = __float2bfloat16(v);
            __nv_bfloat16 lo = __float2bfloat16(v - __bfloat162float(hi));
            uint32_t off = ((uint32_t)t * 256 + (uint32_t)b) * 128 +
                           (((uint32_t)d * 2) ^ (((uint32_t)b & 7) << 4));
            *(__nv_bfloat16*)((char*)g_xA + off) = hi;
            *(__nv_bfloat16*)((char*)g_xA + (size_t)T_ * 32768 + off) = lo;
        }
        uint32_t* hz = (uint32_t*)g_hA;             // buf0, both planes
        for (int i = gtid; i < 131072; i += gn) hz[i] = 0u;
    }

    grid_sync_(1);

    // ---- per-thread fragment addresses ----
    const uint32_t akey = ((uint32_t)(lane & 7)) << 4;
    const uint32_t arow = (uint32_t)(w * 16 + (lane & 15)) * 128;
    uint32_t asw[4];
    #pragma unroll
    for (int ks = 0; ks < 4; ks++)
        asw[ks] = ((uint32_t)(ks * 32 + ((lane >> 4) * 16))) ^ akey;
    uint32_t bo[2];
    {
        uint32_t nrow = (uint32_t)(((lane >> 4) << 3) + (lane & 7));
        bo[0] = nrow * BROW + ((uint32_t)((lane >> 3) & 1)) * 16;
        bo[1] = bo[0] + 16 * BROW;
    }

    float cst[2][2];
    cst[0][0] = cst[0][1] = cst[1][0] = cst[1][1] = 0.f;

    int phf[RD] = {0, 0, 0, 0};
    int phe[RD] = {1, 1, 1, 1};      // fresh barrier: parity-1 wait passes
    unsigned epoch = 2;

    const int jj0 = (lane & 3) * 2;
    const int kc0 = j0 >> 6;
    const int u0  = (j0 & 63) + jj0;

    // ---------------- time loop ----------------
    #pragma unroll 1
    for (int t = 0; t < T_; t++) {
        // producer: fill ring (distributed across warps 0..3)
        #pragma unroll
        for (int j = 0; j < RD; j++) {
            if (w == j && lane == 0) {
                mbar_wait_(mb_e[j], (uint32_t)phe[j]);
                issue_item_(sbase, j, c_order_[j >> 1], j & 1, t, mb_f[j]);
            }
            phe[j] ^= 1;
        }

        float C[4][4];
        #pragma unroll
        for (int n = 0; n < 4; n++)
            #pragma unroll
            for (int q = 0; q < 4; q++) C[n][q] = 0.f;

        uint32_t Bh[4][4][2];

        #pragma unroll 1
        for (int it = 0; it < NITEM; it++) {
            const int s = it & 3;
            const int pl = it & 1;
            mbar_wait_(mb_f[s], (uint32_t)phf[s]);
            phf[s] ^= 1;
            const uint32_t a0 = sbase + SM_A + (uint32_t)s * 32768u;

            if (pl == 0) {
                // hi plane: passes Ah*Bh and Ah*Bl; cache Bh frags
                const uint32_t bb = sbase + SM_B + (uint32_t)c_order_[it >> 1] * 128;
                #pragma unroll
                for (int ks = 0; ks < 4; ks++) {
                    uint32_t Ah[4], r_[4], Bl[4][2];
                    LDM4(Ah, a0 + arow + asw[ks]);
                    LDM4(r_, bb + bo[0] + ks * 32);
                    Bh[ks][0][0] = r_[0]; Bh[ks][0][1] = r_[1];
                    Bh[ks][1][0] = r_[2]; Bh[ks][1][1] = r_[3];
                    LDM4(r_, bb + bo[1] + ks * 32);
                    Bh[ks][2][0] = r_[0]; Bh[ks][2][1] = r_[1];
                    Bh[ks][3][0] = r_[2]; Bh[ks][3][1] = r_[3];
                    LDM4(r_, bb + BPLANE + bo[0] + ks * 32);
                    Bl[0][0] = r_[0]; Bl[0][1] = r_[1];
                    Bl[1][0] = r_[2]; Bl[1][1] = r_[3];
                    LDM4(r_, bb + BPLANE + bo[1] + ks * 32);
                    Bl[2][0] = r_[0]; Bl[2][1] = r_[1];
                    Bl[3][0] = r_[2]; Bl[3][1] = r_[3];
                    #pragma unroll
                    for (int n = 0; n < 4; n++) {
                        MMA(C[n], Ah, Bh[ks][n][0], Bh[ks][n][1]);
                        MMA(C[n], Ah, Bl[n][0], Bl[n][1]);
                    }
                }
            } else {
                // lo plane: pass Al*Bh using cached Bh frags
                #pragma unroll
                for (int ks = 0; ks < 4; ks++) {
                    uint32_t Al[4];
                    LDM4(Al, a0 + arow + asw[ks]);
                    #pragma unroll
                    for (int n = 0; n < 4; n++)
                        MMA(C[n], Al, Bh[ks][n][0], Bh[ks][n][1]);
                }
            }
            if (lane == 0) mbar_arrive_(mb_e[s]);

            // distributed producer: reissue slot for item it+4
            const int j = it + RD;
            if (j < NITEM) {
                const int s2 = j & 3;
                if (w == (j & 15) && lane == 0) {
                    mbar_wait_(mb_e[s2], (uint32_t)phe[s2]);
                    issue_item_(sbase, s2, c_order_[j >> 1], j & 1, t, mb_f[s2]);
                }
                phe[s2] ^= 1;
            }
        }

        // ---- epilogue: gates, write swizzled h (warp-independent) ----
        {
            const int nbuf = (t + 1) & 1;
            char* hb0 = (char*)g_hA + (((size_t)nbuf * 2 + 0) * 8 + kc0) * 32768;
            char* hb1 = hb0 + 8 * 32768;
            #pragma unroll
            for (int rr = 0; rr < 2; rr++) {
                int r = w * 16 + (lane >> 2) + rr * 8;
                float hv[2];
                #pragma unroll
                for (int q = 0; q < 2; q++) {
                    int ci = rr * 2 + q;
                    float iv = sigmoid_(C[0][ci] + bias_s[jj0 + q]);
                    float fv = sigmoid_(C[1][ci] + bias_s[8 + jj0 + q]);
                    float gv = tanh_   (C[2][ci] + bias_s[16 + jj0 + q]);
                    float ov = sigmoid_(C[3][ci] + bias_s[24 + jj0 + q]);
                    cst[rr][q] = fv * cst[rr][q] + iv * gv;
                    hv[q] = ov * tanh_(cst[rr][q]);
                }
                __nv_bfloat16 h0 = __float2bfloat16(hv[0]);
                __nv_bfloat16 h1 = __float2bfloat16(hv[1]);
                __nv_bfloat16 l0 = __float2bfloat16(hv[0] - __bfloat162float(h0));
                __nv_bfloat16 l1 = __float2bfloat16(hv[1] - __bfloat162float(h1));
                uint32_t off = (uint32_t)r * 128 +
                               (((uint32_t)u0 * 2) ^ (((uint32_t)r & 7) << 4));
                *(uint32_t*)(hb0 + off) =
                    (uint32_t)__bfloat16_as_ushort(h0) |
                    ((uint32_t)__bfloat16_as_ushort(h1) << 16);
                *(uint32_t*)(hb1 + off) =
                    (uint32_t)__bfloat16_as_ushort(l0) |
                    ((uint32_t)__bfloat16_as_ushort(l1) << 16);
            }
        }

        grid_sync_(epoch++);
    }

    // ---- final linear: h_last in buf 0 ----
    if (cta == 0 && tid < B_) {
        const int b = tid;
        float s = 0.f;
        #pragma unroll 4
        for (int j = 0; j < H_; j++) {
            uint32_t off = (((uint32_t)(j >> 6)) * 256 + (uint32_t)b) * 128 +
                           (((uint32_t)(j & 63) * 2) ^ (((uint32_t)b & 7) << 4));
            float hv = __bfloat162float(*(const __nv_bfloat16*)((char*)g_hA + off)) +
                       __bfloat162float(*(const __nv_bfloat16*)((char*)g_hA +
                                                                8 * 32768 + off));
            s += hv * __ldg(&lin_w[j]);
        }
        out[b] = s + __ldg(&lin_b[0]);
    }

    __syncthreads();
    if (tid == 0) {
        #pragma unroll
        for (int s = 0; s < RD; s++) {
            mbar_inval_(mb_f[s]);
            mbar_inval_(mb_e[s]);
        }
    }
}

// ---------------- launch ----------------
extern "C" void kernel_launch(void* const* d_in, const int* in_sizes, int n_in,
                              void* d_out, int out_size)
{
    const float* x       = (const float*)d_in[0];
    const float* wih_mu  = (const float*)d_in[1];
    const float* wih_rho = (const float*)d_in[2];
    const float* wih_eps = (const float*)d_in[3];
    const float* whh_mu  = (const float*)d_in[4];
    const float* whh_rho = (const float*)d_in[5];
    const float* whh_eps = (const float*)d_in[6];
    const float* b_mu    = (const float*)d_in[7];
    const float* b_rho   = (const float*)d_in[8];
    const float* b_eps   = (const float*)d_in[9];
    const float* lin_w   = (const float*)d_in[10];
    const float* lin_b   = (const float*)d_in[11];
    float* out = (float*)d_out;

    static int inited = 0;
    if (!inited) {
        cudaFuncSetAttribute(lstm_hmma,
                             cudaFuncAttributeMaxDynamicSharedMemorySize, SMEM_BYTES);
        inited = 1;
    }

    bar_init_kernel<<<1, 1>>>();
    lstm_hmma<<<NCTA, NTHR, SMEM_BYTES>>>(x,
                                          wih_mu, wih_rho, wih_eps,
                                          whh_mu, whh_rho, whh_eps,
                                          b_mu, b_rho, b_eps,
                                          lin_w, lin_b, out);
}

// round 7
// speedup vs baseline: 1.5135x; 1.5135x over previous
#include <cuda_runtime.h>
#include <cuda_bf16.h>
#include <cstdint>

// ---------------- problem constants ----------------
#define B_ 256
#define T_ 512
#define D_ 64
#define H_ 512
#define G_ 2048
#define NCTA 64
#define NTHR 288          // 8 compute warps + 1 producer warp
#define HC 8              // h-columns per CTA (32 gate cols = 4 gates x 8)
#define BROW 1168         // padded B row bytes (9*128 + 16)
#define BPLANE (32 * BROW)

// ---------------- dynamic SMEM layout (bytes) ----------------
#define SM_MBF 0                         // 2 full barriers
#define SM_MBE 64                        // 2 empty barriers
#define SM_BIAS 128
#define SM_A 1024                        // ring: 2 x 65536 (hi+lo planes)
#define SM_B (SM_A + 131072)
#define SMEM_BYTES (SM_B + 2 * BPLANE)   // 206848

// ---------------- persistent device state ----------------
// h K-blocked swizzled, TRIPLE buffered: [buf][plane][kc][row][64]
__device__ __align__(128) __nv_bfloat16 g_hA[3][2][8][256][64];
// x per-step K-blocked swizzled: [plane][t][row][64]
__device__ __align__(128) __nv_bfloat16 g_xA[2][T_][256][64];
__device__ unsigned g_flag[T_ + 1][8];   // readiness of input chunk kc at step t
__device__ unsigned g_count, g_gen;

// ---------------- math helpers ----------------
__device__ __forceinline__ float softplus_(float r) {
    return (r > 15.f) ? r : log1pf(expf(r));
}
__device__ __forceinline__ float sample_(float mu, float rho, float eps) {
    return mu + softplus_(rho) * eps;
}
__device__ __forceinline__ float sigmoid_(float x) {
    return __fdividef(1.f, 1.f + __expf(-x));
}
__device__ __forceinline__ float tanh_(float x) {
    return __fdividef(2.f, 1.f + __expf(-2.f * x)) - 1.f;
}

// ---------------- PTX helpers ----------------
__device__ __forceinline__ uint32_t smem_u32_(const void* p) {
    uint32_t a;
    asm("{ .reg .u64 t; cvta.to.shared.u64 t, %1; cvt.u32.u64 %0, t; }"
        : "=r"(a) : "l"(p));
    return a;
}
__device__ __forceinline__ void mbar_init_(uint32_t a, uint32_t cnt) {
    asm volatile("mbarrier.init.shared.b64 [%0], %1;" :: "r"(a), "r"(cnt) : "memory");
}
__device__ __forceinline__ void mbar_inval_(uint32_t a) {
    asm volatile("mbarrier.inval.shared.b64 [%0];" :: "r"(a) : "memory");
}
__device__ __forceinline__ void mbar_expect_tx_(uint32_t a, uint32_t bytes) {
    asm volatile("mbarrier.arrive.expect_tx.shared.b64 _, [%0], %1;"
                 :: "r"(a), "r"(bytes) : "memory");
}
__device__ __forceinline__ void mbar_arrive_(uint32_t a) {
    asm volatile("mbarrier.arrive.shared.b64 _, [%0];" :: "r"(a) : "memory");
}
__device__ __forceinline__ void mbar_wait_(uint32_t a, uint32_t parity) {
    uint32_t done;
    asm volatile(
        "{\n\t.reg .pred p;\n\t"
        "mbarrier.try_wait.parity.acquire.cta.shared::cta.b64 p, [%1], %2;\n\t"
        "selp.b32 %0, 1, 0, p;\n\t}"
        : "=r"(done) : "r"(a), "r"(parity) : "memory");
    if (!done) {
        asm volatile(
            "{\n\t.reg .pred P1;\n\t"
            "W_%=:\n\t"
            "mbarrier.try_wait.parity.acquire.cta.shared::cta.b64 P1, [%0], %1, 0x989680;\n\t"
            "@P1 bra.uni D_%=;\n\t"
            "bra.uni W_%=;\n\t"
            "D_%=:\n\t}"
            :: "r"(a), "r"(parity) : "memory");
    }
}
__device__ __forceinline__ void bulk_g2s_(uint32_t dst, const void* src,
                                          uint32_t bytes, uint32_t mbar) {
    asm volatile(
        "cp.async.bulk.shared::cluster.global.mbarrier::complete_tx::bytes "
        "[%0], [%1], %2, [%3];"
        :: "r"(dst), "l"(src), "r"(bytes), "r"(mbar) : "memory");
}
__device__ __forceinline__ void flag_wait_(const unsigned* p) {
    unsigned v;
    do {
        asm volatile("ld.global.cg.u32 %0, [%1];" : "=r"(v) : "l"(p));
        if (v >= 8u) break;
        __nanosleep(32);
    } while (1);
    __threadfence();
}

#define LDM4(R, A) \
    asm volatile("ldmatrix.sync.aligned.m8n8.x4.shared.b16 {%0,%1,%2,%3}, [%4];" \
        : "=r"((R)[0]), "=r"((R)[1]), "=r"((R)[2]), "=r"((R)[3]) : "r"(A))

#define MMA(Cf, Af, Bf0, Bf1) \
    asm volatile("mma.sync.aligned.m16n8k16.row.col.f32.bf16.bf16.f32 " \
        "{%0,%1,%2,%3}, {%4,%5,%6,%7}, {%8,%9}, {%0,%1,%2,%3};" \
        : "+f"((Cf)[0]), "+f"((Cf)[1]), "+f"((Cf)[2]), "+f"((Cf)[3]) \
        : "r"((Af)[0]), "r"((Af)[1]), "r"((Af)[2]), "r"((Af)[3]), \
          "r"(Bf0), "r"(Bf1))

extern "C" __global__ void bar_init_kernel() {
    const int tid = threadIdx.x;
    unsigned* f = (unsigned*)g_flag;
    for (int i = tid; i < (T_ + 1) * 8; i += blockDim.x)
        f[i] = (i < 8) ? 8u : 0u;          // step-0 input (zeros) pre-ready
    if (tid == 0) { g_count = 0; g_gen = 0; }
}

// ---------------- one-shot grid barrier (startup only) ----------------
__device__ __forceinline__ void grid_sync_(unsigned target) {
    __syncthreads();
    if (threadIdx.x == 0) {
        __threadfence();
        unsigned a = atomicAdd(&g_count, 1u);
        if (a == NCTA - 1) {
            g_count = 0;
            __threadfence();
            atomicExch(&g_gen, target);
        } else {
            unsigned g;
            do {
                asm volatile("ld.global.cg.u32 %0, [%1];" : "=r"(g) : "l"(&g_gen));
                if (g >= target) break;
                __nanosleep(32);
            } while (1);
        }
        __threadfence();
    }
    __syncthreads();
}

// ---------------- main persistent kernel ----------------
extern "C" __global__ void __launch_bounds__(NTHR, 1)
lstm_hmma(const float* __restrict__ x,
          const float* __restrict__ wih_mu, const float* __restrict__ wih_rho,
          const float* __restrict__ wih_eps,
          const float* __restrict__ whh_mu, const float* __restrict__ whh_rho,
          const float* __restrict__ whh_eps,
          const float* __restrict__ b_mu,   const float* __restrict__ b_rho,
          const float* __restrict__ b_eps,
          const float* __restrict__ lin_w,  const float* __restrict__ lin_b,
          float* __restrict__ out)
{
    extern __shared__ char smem[];
    const uint32_t sbase = smem_u32_(smem);
    const uint32_t mb_f[2] = { sbase + SM_MBF, sbase + SM_MBF + 8 };
    const uint32_t mb_e[2] = { sbase + SM_MBE, sbase + SM_MBE + 8 };
    float* bias_s = (float*)(smem + SM_BIAS);

    const int tid  = threadIdx.x;
    const int lane = tid & 31;
    const int w    = tid >> 5;          // 0..7 compute, 8 producer
    const int cta  = blockIdx.x;
    const int j0   = cta * HC;
    const int kc0  = j0 >> 6;

    if (tid == 0) {
        mbar_init_(mb_f[0], 1); mbar_init_(mb_f[1], 1);
        mbar_init_(mb_e[0], 8); mbar_init_(mb_e[1], 8);
    }

    // ---- sample W into SMEM B planes: rows n (32), cols k (576), padded ----
    for (int idx = tid; idx < 32 * 576; idx += NTHR) {
        int n = idx / 576, k = idx - n * 576;
        int col = (n >> 3) * H_ + j0 + (n & 7);
        float wv;
        if (k < 512) {
            int gi = k * G_ + col;
            wv = sample_(whh_mu[gi], whh_rho[gi], whh_eps[gi]);
        } else {
            int gi = (k - 512) * G_ + col;
            wv = sample_(wih_mu[gi], wih_rho[gi], wih_eps[gi]);
        }
        __nv_bfloat16 hi = __float2bfloat16(wv);
        __nv_bfloat16 lo = __float2bfloat16(wv - __bfloat162float(hi));
        *(__nv_bfloat16*)(smem + SM_B + 0 * BPLANE + n * BROW + k * 2) = hi;
        *(__nv_bfloat16*)(smem + SM_B + 1 * BPLANE + n * BROW + k * 2) = lo;
    }
    if (tid < 32) {
        int col = (tid >> 3) * H_ + j0 + (tid & 7);
        bias_s[tid] = sample_(b_mu[col], b_rho[col], b_eps[col]);
    }

    // ---- build swizzled x planes + zero h buf0 (grid-wide striped) ----
    {
        const int gtid = cta * NTHR + tid;
        const int gn = NCTA * NTHR;
        for (int i = gtid; i < B_ * T_ * D_; i += gn) {
            int d = i & 63, r = i >> 6;
            int t = r & 511, b = r >> 9;            // x is [b][t][d]
            float v = __ldg(&x[i]);
            __nv_bfloat16 hi = __float2bfloat16(v);
            __nv_bfloat16 lo = __float2bfloat16(v - __bfloat162float(hi));
            uint32_t off = ((uint32_t)t * 256 + (uint32_t)b) * 128 +
                           (((uint32_t)d * 2) ^ (((uint32_t)b & 7) << 4));
            *(__nv_bfloat16*)((char*)g_xA + off) = hi;
            *(__nv_bfloat16*)((char*)g_xA + (size_t)T_ * 32768 + off) = lo;
        }
        uint32_t* hz = (uint32_t*)g_hA;             // buf0, both planes
        for (int i = gtid; i < 131072; i += gn) hz[i] = 0u;
    }

    grid_sync_(1);

    // ================= producer warp =================
    if (w == 8) {
        if (lane == 0) {
            int ep[2] = {1, 1};        // fresh barrier: parity-1 wait passes
            unsigned itg = 0;
            #pragma unroll 1
            for (int t = 0; t < T_; t++) {
                const int buf = t % 3;
                #pragma unroll 1
                for (int item = 0; item < 9; item++) {
                    const int s = itg & 1; itg++;
                    mbar_wait_(mb_e[s], (uint32_t)ep[s]); ep[s] ^= 1;
                    const char* src0;
                    if (item == 0) {
                        src0 = (const char*)g_xA + (size_t)t * 32768;
                    } else {
                        const int kc = item - 1;
                        flag_wait_(&g_flag[t][kc]);
                        src0 = (const char*)g_hA +
                               ((size_t)(buf * 2) * 8 + kc) * 32768;
                    }
                    mbar_expect_tx_(mb_f[s], 65536u);
                    const uint32_t dst = sbase + SM_A + (uint32_t)s * 65536u;
                    // hi plane
                    bulk_g2s_(dst, src0, 32768u, mb_f[s]);
                    // lo plane (hi->lo plane stride: x = T_*32768, h = 8*32768)
                    const char* src1 = src0 +
                        ((item == 0) ? (size_t)T_ * 32768 : (size_t)8 * 32768);
                    bulk_g2s_(dst + 32768u, src1, 32768u, mb_f[s]);
                }
            }
        }
        // lanes 1..31 fall through to the tail
    } else {
        // ================= compute warps =================
        const uint32_t akey = ((uint32_t)(lane & 7)) << 4;
        uint32_t arow[2];
        arow[0] = (uint32_t)(w * 32 + (lane & 15)) * 128;
        arow[1] = arow[0] + 16 * 128;
        uint32_t asw[4];
        #pragma unroll
        for (int ks = 0; ks < 4; ks++)
            asw[ks] = ((uint32_t)(ks * 32 + ((lane >> 4) * 16))) ^ akey;
        uint32_t bo[2];
        {
            uint32_t nrow = (uint32_t)(((lane >> 4) << 3) + (lane & 7));
            bo[0] = nrow * BROW + ((uint32_t)((lane >> 3) & 1)) * 16;
            bo[1] = bo[0] + 16 * BROW;
        }

        float cst[4][2];
        #pragma unroll
        for (int rr = 0; rr < 4; rr++) { cst[rr][0] = 0.f; cst[rr][1] = 0.f; }

        int fp[2] = {0, 0};
        unsigned itg = 0;
        const int jj0 = (lane & 3) * 2;
        const int u0  = (j0 & 63) + jj0;

        #pragma unroll 1
        for (int t = 0; t < T_; t++) {
            float C[2][4][4];
            #pragma unroll
            for (int mt = 0; mt < 2; mt++)
                #pragma unroll
                for (int n = 0; n < 4; n++)
                    #pragma unroll
                    for (int q = 0; q < 4; q++) C[mt][n][q] = 0.f;

            #pragma unroll 1
            for (int item = 0; item < 9; item++) {
                const int s = itg & 1; itg++;
                mbar_wait_(mb_f[s], (uint32_t)fp[s]); fp[s] ^= 1;
                const uint32_t a0 = sbase + SM_A + (uint32_t)s * 65536u;
                const uint32_t koff = (item == 0) ? 8u : (uint32_t)(item - 1);
                const uint32_t bb = sbase + SM_B + koff * 128u;

                #pragma unroll
                for (int ks = 0; ks < 4; ks++) {
                    uint32_t Ah[2][4], Al[2][4], Bh[4][2], Bl[4][2], r_[4];
                    #pragma unroll
                    for (int mt = 0; mt < 2; mt++) {
                        LDM4(Ah[mt], a0 + arow[mt] + asw[ks]);
                        LDM4(Al[mt], a0 + 32768 + arow[mt] + asw[ks]);
                    }
                    LDM4(r_, bb + bo[0] + ks * 32);
                    Bh[0][0] = r_[0]; Bh[0][1] = r_[1];
                    Bh[1][0] = r_[2]; Bh[1][1] = r_[3];
                    LDM4(r_, bb + bo[1] + ks * 32);
                    Bh[2][0] = r_[0]; Bh[2][1] = r_[1];
                    Bh[3][0] = r_[2]; Bh[3][1] = r_[3];
                    LDM4(r_, bb + BPLANE + bo[0] + ks * 32);
                    Bl[0][0] = r_[0]; Bl[0][1] = r_[1];
                    Bl[1][0] = r_[2]; Bl[1][1] = r_[3];
                    LDM4(r_, bb + BPLANE + bo[1] + ks * 32);
                    Bl[2][0] = r_[0]; Bl[2][1] = r_[1];
                    Bl[3][0] = r_[2]; Bl[3][1] = r_[3];
                    #pragma unroll
                    for (int mt = 0; mt < 2; mt++)
                        #pragma unroll
                        for (int n = 0; n < 4; n++) {
                            MMA(C[mt][n], Ah[mt], Bh[n][0], Bh[n][1]);
                            MMA(C[mt][n], Ah[mt], Bl[n][0], Bl[n][1]);
                            MMA(C[mt][n], Al[mt], Bh[n][0], Bh[n][1]);
                        }
                }
                if (lane == 0) mbar_arrive_(mb_e[s]);
            }

            // ---- epilogue: gates, write h to buf (t+1)%3, publish flag ----
            {
                const int nbuf = (t + 1) % 3;
                char* hb0 = (char*)g_hA +
                            (((size_t)nbuf * 2 + 0) * 8 + kc0) * 32768;
                char* hb1 = hb0 + 8 * 32768;
                #pragma unroll
                for (int rr = 0; rr < 4; rr++) {
                    int r = w * 32 + (lane >> 2) + rr * 8;
                    int mt = rr >> 1, ci = (rr & 1) * 2;
                    float hv[2];
                    #pragma unroll
                    for (int q = 0; q < 2; q++) {
                        float iv = sigmoid_(C[mt][0][ci + q] + bias_s[jj0 + q]);
                        float fv = sigmoid_(C[mt][1][ci + q] + bias_s[8 + jj0 + q]);
                        float gv = tanh_   (C[mt][2][ci + q] + bias_s[16 + jj0 + q]);
                        float ov = sigmoid_(C[mt][3][ci + q] + bias_s[24 + jj0 + q]);
                        cst[rr][q] = fv * cst[rr][q] + iv * gv;
                        hv[q] = ov * tanh_(cst[rr][q]);
                    }
                    __nv_bfloat16 h0 = __float2bfloat16(hv[0]);
                    __nv_bfloat16 h1 = __float2bfloat16(hv[1]);
                    __nv_bfloat16 l0 = __float2bfloat16(hv[0] - __bfloat162float(h0));
                    __nv_bfloat16 l1 = __float2bfloat16(hv[1] - __bfloat162float(h1));
                    uint32_t off = (uint32_t)r * 128 +
                                   (((uint32_t)u0 * 2) ^ (((uint32_t)r & 7) << 4));
                    *(uint32_t*)(hb0 + off) =
                        (uint32_t)__bfloat16_as_ushort(h0) |
                        ((uint32_t)__bfloat16_as_ushort(h1) << 16);
                    *(uint32_t*)(hb1 + off) =
                        (uint32_t)__bfloat16_as_ushort(l0) |
                        ((uint32_t)__bfloat16_as_ushort(l1) << 16);
                }
            }
            __threadfence();
            asm volatile("bar.sync 1, 256;" ::: "memory");   // compute warps only
            if (tid == 0) atomicAdd(&g_flag[t + 1][kc0], 1u);
        }

        // ---- final linear: h_last = input of step 512 -> buf 512%3 = 2 ----
        if (cta == 0) {
            if (tid == 0) {
                #pragma unroll
                for (int kc = 0; kc < 8; kc++) flag_wait_(&g_flag[T_][kc]);
            }
            asm volatile("bar.sync 1, 256;" ::: "memory");
            const int b = tid;
            float s = 0.f;
            const char* hibase = (const char*)g_hA + (size_t)4 * 262144;
            const char* lobase = (const char*)g_hA + (size_t)5 * 262144;
            #pragma unroll 4
            for (int j = 0; j < H_; j++) {
                uint32_t off = (((uint32_t)(j >> 6)) * 256 + (uint32_t)b) * 128 +
                               (((uint32_t)(j & 63) * 2) ^ (((uint32_t)b & 7) << 4));
                float hv = __bfloat162float(*(const __nv_bfloat16*)(hibase + off)) +
                           __bfloat162float(*(const __nv_bfloat16*)(lobase + off));
                s += hv * __ldg(&lin_w[j]);
            }
            out[b] = s + __ldg(&lin_b[0]);
        }
    }

    __syncthreads();
    if (tid == 0) {
        mbar_inval_(mb_f[0]); mbar_inval_(mb_f[1]);
        mbar_inval_(mb_e[0]); mbar_inval_(mb_e[1]);
    }
}

// ---------------- launch ----------------
extern "C" void kernel_launch(void* const* d_in, const int* in_sizes, int n_in,
                              void* d_out, int out_size)
{
    const float* x       = (const float*)d_in[0];
    const float* wih_mu  = (const float*)d_in[1];
    const float* wih_rho = (const float*)d_in[2];
    const float* wih_eps = (const float*)d_in[3];
    const float* whh_mu  = (const float*)d_in[4];
    const float* whh_rho = (const float*)d_in[5];
    const float* whh_eps = (const float*)d_in[6];
    const float* b_mu    = (const float*)d_in[7];
    const float* b_rho   = (const float*)d_in[8];
    const float* b_eps   = (const float*)d_in[9];
    const float* lin_w   = (const float*)d_in[10];
    const float* lin_b   = (const float*)d_in[11];
    float* out = (float*)d_out;

    static int inited = 0;
    if (!inited) {
        cudaFuncSetAttribute(lstm_hmma,
                             cudaFuncAttributeMaxDynamicSharedMemorySize, SMEM_BYTES);
        inited = 1;
    }

    bar_init_kernel<<<1, 256>>>();
    lstm_hmma<<<NCTA, NTHR, SMEM_BYTES>>>(x,
                                          wih_mu, wih_rho, wih_eps,
                                          whh_mu, whh_rho, whh_eps,
                                          b_mu, b_rho, b_eps,
                                          lin_w, lin_b, out);
}

// round 8
// speedup vs baseline: 1.7166x; 1.1342x over previous
#include <cuda_runtime.h>
#include <cuda_bf16.h>
#include <cstdint>

// ---------------- problem constants ----------------
#define B_ 256
#define T_ 512
#define D_ 64
#define H_ 512
#define G_ 2048
#define NCTA 128
#define NTHR 544          // 16 compute warps + 1 producer warp
#define NCW 16            // compute warps
#define HC 4              // h-columns per CTA (16 gate cols)
#define NCOL 16           // gate cols per CTA
#define FLAGTGT 16u       // CTAs producing each 64-col chunk
#define BROW 1168         // padded B row bytes (9*128 + 16)
#define BPLANE (NCOL * BROW)

// ---------------- dynamic SMEM layout (bytes) ----------------
#define SM_MBF 0                         // 2 full barriers
#define SM_MBE 64                        // 2 empty barriers
#define SM_BIAS 128
#define SM_A 1024                        // ring: 2 x 65536 (hi+lo planes)
#define SM_B (SM_A + 131072)
#define SMEM_BYTES (SM_B + 2 * BPLANE)   // ~170KB

// ---------------- persistent device state ----------------
// h K-blocked swizzled, TRIPLE buffered: [buf][plane][kc][row][64]
__device__ __align__(128) __nv_bfloat16 g_hA[3][2][8][256][64];
// x per-step K-blocked swizzled: [plane][t][row][64]
__device__ __align__(128) __nv_bfloat16 g_xA[2][T_][256][64];
__device__ unsigned g_flag[T_ + 1][8];   // readiness of input chunk kc at step t
__device__ unsigned g_count, g_gen;

// ---------------- math helpers ----------------
__device__ __forceinline__ float softplus_(float r) {
    return (r > 15.f) ? r : log1pf(expf(r));
}
__device__ __forceinline__ float sample_(float mu, float rho, float eps) {
    return mu + softplus_(rho) * eps;
}
__device__ __forceinline__ float sigmoid_(float x) {
    return __fdividef(1.f, 1.f + __expf(-x));
}
__device__ __forceinline__ float tanh_(float x) {
    return __fdividef(2.f, 1.f + __expf(-2.f * x)) - 1.f;
}

// ---------------- PTX helpers ----------------
__device__ __forceinline__ uint32_t smem_u32_(const void* p) {
    uint32_t a;
    asm("{ .reg .u64 t; cvta.to.shared.u64 t, %1; cvt.u32.u64 %0, t; }"
        : "=r"(a) : "l"(p));
    return a;
}
__device__ __forceinline__ void mbar_init_(uint32_t a, uint32_t cnt) {
    asm volatile("mbarrier.init.shared.b64 [%0], %1;" :: "r"(a), "r"(cnt) : "memory");
}
__device__ __forceinline__ void mbar_inval_(uint32_t a) {
    asm volatile("mbarrier.inval.shared.b64 [%0];" :: "r"(a) : "memory");
}
__device__ __forceinline__ void mbar_expect_tx_(uint32_t a, uint32_t bytes) {
    asm volatile("mbarrier.arrive.expect_tx.shared.b64 _, [%0], %1;"
                 :: "r"(a), "r"(bytes) : "memory");
}
__device__ __forceinline__ void mbar_arrive_(uint32_t a) {
    asm volatile("mbarrier.arrive.shared.b64 _, [%0];" :: "r"(a) : "memory");
}
__device__ __forceinline__ void mbar_wait_(uint32_t a, uint32_t parity) {
    uint32_t done;
    asm volatile(
        "{\n\t.reg .pred p;\n\t"
        "mbarrier.try_wait.parity.acquire.cta.shared::cta.b64 p, [%1], %2;\n\t"
        "selp.b32 %0, 1, 0, p;\n\t}"
        : "=r"(done) : "r"(a), "r"(parity) : "memory");
    if (!done) {
        asm volatile(
            "{\n\t.reg .pred P1;\n\t"
            "W_%=:\n\t"
            "mbarrier.try_wait.parity.acquire.cta.shared::cta.b64 P1, [%0], %1, 0x989680;\n\t"
            "@P1 bra.uni D_%=;\n\t"
            "bra.uni W_%=;\n\t"
            "D_%=:\n\t}"
            :: "r"(a), "r"(parity) : "memory");
    }
}
__device__ __forceinline__ void bulk_g2s_(uint32_t dst, const void* src,
                                          uint32_t bytes, uint32_t mbar) {
    asm volatile(
        "cp.async.bulk.shared::cluster.global.mbarrier::complete_tx::bytes "
        "[%0], [%1], %2, [%3];"
        :: "r"(dst), "l"(src), "r"(bytes), "r"(mbar) : "memory");
}
__device__ __forceinline__ void flag_wait_(const unsigned* p) {
    unsigned v;
    do {
        asm volatile("ld.global.cg.u32 %0, [%1];" : "=r"(v) : "l"(p));
        if (v >= FLAGTGT) break;
        __nanosleep(32);
    } while (1);
    __threadfence();
}

#define LDM4(R, A) \
    asm volatile("ldmatrix.sync.aligned.m8n8.x4.shared.b16 {%0,%1,%2,%3}, [%4];" \
        : "=r"((R)[0]), "=r"((R)[1]), "=r"((R)[2]), "=r"((R)[3]) : "r"(A))

#define MMA(Cf, Af, Bf0, Bf1) \
    asm volatile("mma.sync.aligned.m16n8k16.row.col.f32.bf16.bf16.f32 " \
        "{%0,%1,%2,%3}, {%4,%5,%6,%7}, {%8,%9}, {%0,%1,%2,%3};" \
        : "+f"((Cf)[0]), "+f"((Cf)[1]), "+f"((Cf)[2]), "+f"((Cf)[3]) \
        : "r"((Af)[0]), "r"((Af)[1]), "r"((Af)[2]), "r"((Af)[3]), \
          "r"(Bf0), "r"(Bf1))

extern "C" __global__ void bar_init_kernel() {
    const int tid = threadIdx.x;
    unsigned* f = (unsigned*)g_flag;
    for (int i = tid; i < (T_ + 1) * 8; i += blockDim.x)
        f[i] = (i < 8) ? FLAGTGT : 0u;     // step-0 input (zeros) pre-ready
    if (tid == 0) { g_count = 0; g_gen = 0; }
}

// ---------------- one-shot grid barrier (startup only) ----------------
__device__ __forceinline__ void grid_sync_(unsigned target) {
    __syncthreads();
    if (threadIdx.x == 0) {
        __threadfence();
        unsigned a = atomicAdd(&g_count, 1u);
        if (a == NCTA - 1) {
            g_count = 0;
            __threadfence();
            atomicExch(&g_gen, target);
        } else {
            unsigned g;
            do {
                asm volatile("ld.global.cg.u32 %0, [%1];" : "=r"(g) : "l"(&g_gen));
                if (g >= target) break;
                __nanosleep(32);
            } while (1);
        }
        __threadfence();
    }
    __syncthreads();
}

// gate/hcol mapping within the 16 local cols: all 4 gates of one h-col land in
// one lane's C fragment columns (no epilogue shuffles).
__device__ __forceinline__ int colmap_(int n, int j0) {
    int gate = ((n >> 3) << 1) | (n & 1);
    int hcol = (n >> 1) & 3;
    return gate * H_ + j0 + hcol;
}

// ---------------- main persistent kernel ----------------
extern "C" __global__ void __launch_bounds__(NTHR, 1)
lstm_hmma(const float* __restrict__ x,
          const float* __restrict__ wih_mu, const float* __restrict__ wih_rho,
          const float* __restrict__ wih_eps,
          const float* __restrict__ whh_mu, const float* __restrict__ whh_rho,
          const float* __restrict__ whh_eps,
          const float* __restrict__ b_mu,   const float* __restrict__ b_rho,
          const float* __restrict__ b_eps,
          const float* __restrict__ lin_w,  const float* __restrict__ lin_b,
          float* __restrict__ out)
{
    extern __shared__ char smem[];
    const uint32_t sbase = smem_u32_(smem);
    const uint32_t mb_f[2] = { sbase + SM_MBF, sbase + SM_MBF + 8 };
    const uint32_t mb_e[2] = { sbase + SM_MBE, sbase + SM_MBE + 8 };
    float* bias_s = (float*)(smem + SM_BIAS);

    const int tid  = threadIdx.x;
    const int lane = tid & 31;
    const int w    = tid >> 5;          // 0..15 compute, 16 producer
    const int cta  = blockIdx.x;
    const int j0   = cta * HC;
    const int kc0  = j0 >> 6;

    if (tid == 0) {
        mbar_init_(mb_f[0], 1); mbar_init_(mb_f[1], 1);
        mbar_init_(mb_e[0], NCW); mbar_init_(mb_e[1], NCW);
    }

    // ---- sample W into SMEM B planes: rows n (16), cols k (576), padded ----
    for (int idx = tid; idx < NCOL * 576; idx += NTHR) {
        int n = idx / 576, k = idx - n * 576;
        int col = colmap_(n, j0);
        float wv;
        if (k < 512) {
            int gi = k * G_ + col;
            wv = sample_(whh_mu[gi], whh_rho[gi], whh_eps[gi]);
        } else {
            int gi = (k - 512) * G_ + col;
            wv = sample_(wih_mu[gi], wih_rho[gi], wih_eps[gi]);
        }
        __nv_bfloat16 hi = __float2bfloat16(wv);
        __nv_bfloat16 lo = __float2bfloat16(wv - __bfloat162float(hi));
        *(__nv_bfloat16*)(smem + SM_B + 0 * BPLANE + n * BROW + k * 2) = hi;
        *(__nv_bfloat16*)(smem + SM_B + 1 * BPLANE + n * BROW + k * 2) = lo;
    }
    if (tid < NCOL) {
        bias_s[tid] = sample_(b_mu[colmap_(tid, j0)], b_rho[colmap_(tid, j0)],
                              b_eps[colmap_(tid, j0)]);
    }

    // ---- build swizzled x planes + zero h buf0 (grid-wide striped) ----
    {
        const int gtid = cta * NTHR + tid;
        const int gn = NCTA * NTHR;
        for (int i = gtid; i < B_ * T_ * D_; i += gn) {
            int d = i & 63, r = i >> 6;
            int t = r & 511, b = r >> 9;            // x is [b][t][d]
            float v = __ldg(&x[i]);
            __nv_bfloat16 hi = __float2bfloat16(v);
            __nv_bfloat16 lo = __float2bfloat16(v - __bfloat162float(hi));
            uint32_t off = ((uint32_t)t * 256 + (uint32_t)b) * 128 +
                           (((uint32_t)d * 2) ^ (((uint32_t)b & 7) << 4));
            *(__nv_bfloat16*)((char*)g_xA + off) = hi;
            *(__nv_bfloat16*)((char*)g_xA + (size_t)T_ * 32768 + off) = lo;
        }
        uint32_t* hz = (uint32_t*)g_hA;             // buf0, both planes
        for (int i = gtid; i < 131072; i += gn) hz[i] = 0u;
    }

    grid_sync_(1);

    // ================= producer warp =================
    if (w == NCW) {
        if (lane == 0) {
            int ep[2] = {1, 1};        // fresh barrier: parity-1 wait passes
            unsigned itg = 0;
            #pragma unroll 1
            for (int t = 0; t < T_; t++) {
                const int buf = t % 3;
                #pragma unroll 1
                for (int item = 0; item < 9; item++) {
                    const int s = itg & 1; itg++;
                    mbar_wait_(mb_e[s], (uint32_t)ep[s]); ep[s] ^= 1;
                    const char* src0;
                    if (item == 0) {
                        src0 = (const char*)g_xA + (size_t)t * 32768;
                    } else {
                        const int kc = item - 1;
                        flag_wait_(&g_flag[t][kc]);
                        src0 = (const char*)g_hA +
                               ((size_t)(buf * 2) * 8 + kc) * 32768;
                    }
                    mbar_expect_tx_(mb_f[s], 65536u);
                    const uint32_t dst = sbase + SM_A + (uint32_t)s * 65536u;
                    bulk_g2s_(dst, src0, 32768u, mb_f[s]);
                    const char* src1 = src0 +
                        ((item == 0) ? (size_t)T_ * 32768 : (size_t)8 * 32768);
                    bulk_g2s_(dst + 32768u, src1, 32768u, mb_f[s]);
                }
            }
        }
    } else {
        // ================= compute warps =================
        const uint32_t akey = ((uint32_t)(lane & 7)) << 4;
        const uint32_t arow = (uint32_t)(w * 16 + (lane & 15)) * 128;
        uint32_t asw[4];
        #pragma unroll
        for (int ks = 0; ks < 4; ks++)
            asw[ks] = ((uint32_t)(ks * 32 + ((lane >> 4) * 16))) ^ akey;
        uint32_t bo;
        {
            uint32_t nrow = (uint32_t)(((lane >> 4) << 3) + (lane & 7));
            bo = nrow * BROW + ((uint32_t)((lane >> 3) & 1)) * 16;
        }

        float cst[2] = {0.f, 0.f};      // c state: rows r, r+8 (one hcol/lane)

        int fp[2] = {0, 0};
        unsigned itg = 0;
        const int L  = lane & 3;                 // local h-col
        const int u0 = (j0 & 63) + L;            // col within 64-col chunk

        #pragma unroll 1
        for (int t = 0; t < T_; t++) {
            float C[2][4];
            #pragma unroll
            for (int n = 0; n < 2; n++)
                #pragma unroll
                for (int q = 0; q < 4; q++) C[n][q] = 0.f;

            #pragma unroll 1
            for (int item = 0; item < 9; item++) {
                const int s = itg & 1; itg++;
                mbar_wait_(mb_f[s], (uint32_t)fp[s]); fp[s] ^= 1;
                const uint32_t a0 = sbase + SM_A + (uint32_t)s * 65536u;
                const uint32_t koff = (item == 0) ? 8u : (uint32_t)(item - 1);
                const uint32_t bb = sbase + SM_B + koff * 128u;

                #pragma unroll
                for (int ks = 0; ks < 4; ks++) {
                    uint32_t Ah[4], Al[4], Bh[4], Bl[4];
                    LDM4(Ah, a0 + arow + asw[ks]);
                    LDM4(Al, a0 + 32768 + arow + asw[ks]);
                    LDM4(Bh, bb + bo + ks * 32);
                    LDM4(Bl, bb + BPLANE + bo + ks * 32);
                    MMA(C[0], Ah, Bh[0], Bh[1]);
                    MMA(C[1], Ah, Bh[2], Bh[3]);
                    MMA(C[0], Ah, Bl[0], Bl[1]);
                    MMA(C[1], Ah, Bl[2], Bl[3]);
                    MMA(C[0], Al, Bh[0], Bh[1]);
                    MMA(C[1], Al, Bh[2], Bh[3]);
                }
                if (lane == 0) mbar_arrive_(mb_e[s]);
            }

            // ---- epilogue: 2 rows x 1 hcol per lane, write h, publish flag ----
            {
                const int nbuf = (t + 1) % 3;
                char* hb0 = (char*)g_hA +
                            (((size_t)nbuf * 2 + 0) * 8 + kc0) * 32768;
                char* hb1 = hb0 + 8 * 32768;
                #pragma unroll
                for (int rr = 0; rr < 2; rr++) {
                    const int r = w * 16 + (lane >> 2) + rr * 8;
                    const int c = rr * 2;
                    float iv = sigmoid_(C[0][c]     + bias_s[2 * L]);
                    float fv = sigmoid_(C[0][c + 1] + bias_s[2 * L + 1]);
                    float gv = tanh_   (C[1][c]     + bias_s[8 + 2 * L]);
                    float ov = sigmoid_(C[1][c + 1] + bias_s[8 + 2 * L + 1]);
                    cst[rr] = fv * cst[rr] + iv * gv;
                    float hval = ov * tanh_(cst[rr]);
                    __nv_bfloat16 hi = __float2bfloat16(hval);
                    __nv_bfloat16 lo =
                        __float2bfloat16(hval - __bfloat162float(hi));
                    uint32_t off = (uint32_t)r * 128 +
                                   (((uint32_t)u0 * 2) ^ (((uint32_t)r & 7) << 4));
                    *(__nv_bfloat16*)(hb0 + off) = hi;
                    *(__nv_bfloat16*)(hb1 + off) = lo;
                }
            }
            __threadfence();
            asm volatile("bar.sync 1, 512;" ::: "memory");  // compute warps only
            if (tid == 0) atomicAdd(&g_flag[t + 1][kc0], 1u);
        }

        // ---- final linear: h_last = input of step 512 -> buf 512%3 = 2 ----
        if (cta == 0) {
            if (tid == 0) {
                #pragma unroll
                for (int kc = 0; kc < 8; kc++) flag_wait_(&g_flag[T_][kc]);
            }
            asm volatile("bar.sync 1, 512;" ::: "memory");
            if (tid < B_) {
                const int b = tid;
                float s = 0.f;
                const char* hibase = (const char*)g_hA + (size_t)4 * 262144;
                const char* lobase = (const char*)g_hA + (size_t)5 * 262144;
                #pragma unroll 4
                for (int j = 0; j < H_; j++) {
                    uint32_t off =
                        (((uint32_t)(j >> 6)) * 256 + (uint32_t)b) * 128 +
                        (((uint32_t)(j & 63) * 2) ^ (((uint32_t)b & 7) << 4));
                    float hv =
                        __bfloat162float(*(const __nv_bfloat16*)(hibase + off)) +
                        __bfloat162float(*(const __nv_bfloat16*)(lobase + off));
                    s += hv * __ldg(&lin_w[j]);
                }
                out[b] = s + __ldg(&lin_b[0]);
            }
        }
    }

    __syncthreads();
    if (tid == 0) {
        mbar_inval_(mb_f[0]); mbar_inval_(mb_f[1]);
        mbar_inval_(mb_e[0]); mbar_inval_(mb_e[1]);
    }
}

// ---------------- launch ----------------
extern "C" void kernel_launch(void* const* d_in, const int* in_sizes, int n_in,
                              void* d_out, int out_size)
{
    const float* x       = (const float*)d_in[0];
    const float* wih_mu  = (const float*)d_in[1];
    const float* wih_rho = (const float*)d_in[2];
    const float* wih_eps = (const float*)d_in[3];
    const float* whh_mu  = (const float*)d_in[4];
    const float* whh_rho = (const float*)d_in[5];
    const float* whh_eps = (const float*)d_in[6];
    const float* b_mu    = (const float*)d_in[7];
    const float* b_rho   = (const float*)d_in[8];
    const float* b_eps   = (const float*)d_in[9];
    const float* lin_w   = (const float*)d_in[10];
    const float* lin_b   = (const float*)d_in[11];
    float* out = (float*)d_out;

    static int inited = 0;
    if (!inited) {
        cudaFuncSetAttribute(lstm_hmma,
                             cudaFuncAttributeMaxDynamicSharedMemorySize, SMEM_BYTES);
        inited = 1;
    }

    bar_init_kernel<<<1, 256>>>();
    lstm_hmma<<<NCTA, NTHR, SMEM_BYTES>>>(x,
                                          wih_mu, wih_rho, wih_eps,
                                          whh_mu, whh_rho, whh_eps,
                                          b_mu, b_rho, b_eps,
                                          lin_w, lin_b, out);
}